// round 8
// baseline (speedup 1.0000x reference)
#include <cuda_runtime.h>
#include <math.h>

#define BB 32
#define CC 3
#define HH 512
#define WW 512
#define HW (HH * WW)
#define PI_F 3.14159f

// Scratch: per-batch inverse homographies, light params, batch-invariant
// moire field (3 MB, L2-resident, reused 32x).
__device__ float g_minv[BB][9];
__device__ float g_light[3];   // xf, yf, 1/max_len
__device__ float g_moire[CC * HW];

// ---------------------------------------------------------------------------
// Prep: moire field (4 px/thread, float4 stores) + block-0 side jobs:
// closed-form (Heckbert) homography per batch in fp32 and light params.
// Homography is unique up to scale and only used through a perspective
// divide, so the adjugate (un-normalized inverse) suffices.
// ---------------------------------------------------------------------------
__global__ void prep_kernel(const float* __restrict__ theta,
                            const float* __restrict__ center,
                            const float* __restrict__ dst_offsets,
                            const int* __restrict__ light_xy) {
    if (blockIdx.x == 0) {
        int b = threadIdx.x;
        if (b == 32) {
            float xf = (float)light_xy[0];
            float yf = (float)light_xy[1];
            const float S = 512.0f;
            float d0 = sqrtf(xf * xf + yf * yf);
            float d1 = sqrtf((xf - S) * (xf - S) + yf * yf);
            float d2 = sqrtf(xf * xf + (yf - S) * (yf - S));
            float d3 = sqrtf((xf - S) * (xf - S) + (yf - S) * (yf - S));
            float ml = fmaxf(fmaxf(d0, d1), fmaxf(d2, d3)) * 0.5f;
            g_light[0] = xf;
            g_light[1] = yf;
            g_light[2] = 1.0f / ml;
        }
        if (b < BB) {
            const float S = 512.0f;
            // src corners: k=0:(0,0) k=1:(0,S) k=2:(S,0) k=3:(S,S)
            const float sxc[4] = {0.0f, 0.0f, 512.0f, 512.0f};
            const float syc[4] = {0.0f, 512.0f, 0.0f, 512.0f};
            float du[4], dv[4];
            for (int k = 0; k < 4; k++) {
                du[k] = sxc[k] + dst_offsets[(b * 4 + k) * 2 + 0];
                dv[k] = syc[k] + dst_offsets[(b * 4 + k) * 2 + 1];
            }
            // Unit-square param: (0,0)->dst0 (1,0)->dst2 (1,1)->dst3 (0,1)->dst1
            float u0 = du[0], u1 = du[2], u2 = du[3], u3 = du[1];
            float v0 = dv[0], v1 = dv[2], v2 = dv[3], v3 = dv[1];
            float sx = u0 - u1 + u2 - u3;
            float sy = v0 - v1 + v2 - v3;
            float dx1 = u1 - u2, dx2 = u3 - u2;
            float dy1 = v1 - v2, dy2 = v3 - v2;
            float den = dx1 * dy2 - dy1 * dx2;
            float g = (sx * dy2 - sy * dx2) / den;
            float h = (dx1 * sy - dy1 * sx) / den;
            float a = u1 - u0 + g * u1;
            float bq = u3 - u0 + h * u3;
            float c = u0;
            float d = v1 - v0 + g * v1;
            float e = v3 - v0 + h * v3;
            float f = v0;
            float m0 = a,  m1 = bq, m2 = c * S;
            float m3 = d,  m4 = e,  m5 = f * S;
            float m6 = g,  m7 = h,  m8 = S;
            float inv9[9] = {
                m4 * m8 - m5 * m7, m2 * m7 - m1 * m8, m1 * m5 - m2 * m4,
                m5 * m6 - m3 * m8, m0 * m8 - m2 * m6, m2 * m3 - m0 * m5,
                m3 * m7 - m4 * m6, m1 * m6 - m0 * m7, m0 * m4 - m1 * m3};
            float nrm = 1.0f / inv9[8];
            for (int k = 0; k < 9; k++) g_minv[b][k] = inv9[k] * nrm;
        }
    }

    int idx4 = (blockIdx.x * blockDim.x + threadIdx.x) * 4;
    if (idx4 >= CC * HW) return;
    int c = idx4 / HW;
    int rem = idx4 - c * HW;
    int i = rem >> 9;
    int j0 = rem & (WW - 1);   // 4-aligned, all 4 cols in same row

    float cx = center[c * 2 + 0];
    float cy = center[c * 2 + 1];
    float th = theta[c] / 180.0f * PI_F;
    float cth = cosf(th), sth = sinf(th);
    float dx = (float)i - cx;
    float dx2 = dx * dx;
    float si = sth * (float)i;

    float4 m4v;
    float* mp = &m4v.x;
#pragma unroll
    for (int q = 0; q < 4; q++) {
        float jj = (float)(j0 + q);
        float dy = jj - cy;
        float z1 = 0.5f + 0.5f * cosf(2.0f * PI_F * sqrtf(dx2 + dy * dy));
        float z2 = 0.5f + 0.5f * cosf(cth * jj + si);
        mp[q] = fminf(z1, z2) * 2.0f - 1.0f;
    }
    *reinterpret_cast<float4*>(g_moire + idx4) = m4v;
}

// ---------------------------------------------------------------------------
// Fused main kernel: 4 px/thread, float4 streaming I/O with evict-streaming
// cache hints (L2 reserved for the gather window + moire), interior fast
// path for bilinear taps, cover pass-through folded in.
// ---------------------------------------------------------------------------
__global__ void __launch_bounds__(256, 4)
main_kernel(const float* __restrict__ imgs,
            const float* __restrict__ noise,
            const float* __restrict__ cover,
            const float* __restrict__ hue_shift,
            const float* __restrict__ bright,
            const float* __restrict__ contrast,
            float* __restrict__ out) {
    int t = blockIdx.x * blockDim.x + threadIdx.x;
    int p4 = t * 4;                 // first pixel of the quad
    if (p4 >= HW) return;
    int b = blockIdx.y;
    int i = p4 >> 9;                // row (same for all 4 pixels)
    int j0 = p4 & (WW - 1);

    const size_t n_img = (size_t)BB * CC * HW;
    size_t base = (size_t)b * CC * HW + p4;

    // Streaming loads first (independent of the gather chain; no L2 reuse ->
    // evict-streaming; moire has 32x reuse -> default policy).
    float4 nz[3], cv[3], mo[3];
#pragma unroll
    for (int c = 0; c < 3; c++) {
        nz[c] = __ldcs(reinterpret_cast<const float4*>(noise + base + (size_t)c * HW));
        cv[c] = __ldcs(reinterpret_cast<const float4*>(cover + base + (size_t)c * HW));
        mo[c] = __ldg(reinterpret_cast<const float4*>(g_moire + c * HW + p4));
    }

    // Projective map (row-constant parts hoisted).
    const float* mv = g_minv[b];
    float y = (float)i;
    float cA = mv[1] * y + mv[2];
    float cB = mv[4] * y + mv[5];
    float cW = mv[7] * y + mv[8];

    int ix0[4], iy0[4];
    float wx[4], wy[4];
    bool interior = true;
#pragma unroll
    for (int q = 0; q < 4; q++) {
        float x = (float)(j0 + q);
        float invw = __fdividef(1.0f, mv[6] * x + cW);
        float sxv = (mv[0] * x + cA) * invw;
        float syv = (mv[3] * x + cB) * invw;
        float x0f = floorf(sxv), y0f = floorf(syv);
        wx[q] = sxv - x0f;
        wy[q] = syv - y0f;
        ix0[q] = (int)x0f;
        iy0[q] = (int)y0f;
        interior &= ((unsigned)ix0[q] <= (unsigned)(WW - 2)) &&
                    ((unsigned)iy0[q] <= (unsigned)(HH - 2));
    }

    float ct = contrast[b];
    float br = bright[b];
    float hs0 = hue_shift[b * 3 + 0];
    float hs1 = hue_shift[b * 3 + 1];
    float hs2 = hue_shift[b * 3 + 2];

    const float* imb = imgs + (size_t)b * CC * HW;
    float v[3][4];
    if (interior) {
        // Fast path: all taps in-bounds, raw indices, no masks.
        int o00[4];
#pragma unroll
        for (int q = 0; q < 4; q++) o00[q] = iy0[q] * WW + ix0[q];
#pragma unroll
        for (int c = 0; c < 3; c++) {
            const float* im = imb + c * HW;
            float hs = (c == 0) ? hs0 : ((c == 1) ? hs1 : hs2);
#pragma unroll
            for (int q = 0; q < 4; q++) {
                float v00 = im[o00[q]];
                float v01 = im[o00[q] + 1];
                float v10 = im[o00[q] + WW];
                float v11 = im[o00[q] + WW + 1];
                float top = v00 + wx[q] * (v01 - v00);
                float bot = v10 + wx[q] * (v11 - v10);
                float val = top + wy[q] * (bot - top);
                float o = val * ct + hs + br;
                v[c][q] = fminf(fmaxf(o, -1.0f), 1.0f);
            }
        }
    } else {
        // Boundary path: kornia zero-padding semantics (mask, clamp).
#pragma unroll
        for (int c = 0; c < 3; c++) {
            const float* im = imb + c * HW;
            float hs = (c == 0) ? hs0 : ((c == 1) ? hs1 : hs2);
#pragma unroll
            for (int q = 0; q < 4; q++) {
                int x0 = ix0[q], y0 = iy0[q];
                int x1 = x0 + 1, y1 = y0 + 1;
                bool vx0 = (x0 >= 0) && (x0 < WW);
                bool vx1 = (x1 >= 0) && (x1 < WW);
                bool vy0 = (y0 >= 0) && (y0 < HH);
                bool vy1 = (y1 >= 0) && (y1 < HH);
                int cx0 = min(max(x0, 0), WW - 1);
                int cx1 = min(max(x1, 0), WW - 1);
                int cy0 = min(max(y0, 0), HH - 1) * WW;
                int cy1 = min(max(y1, 0), HH - 1) * WW;
                float v00 = (vy0 && vx0) ? im[cy0 + cx0] : 0.0f;
                float v01 = (vy0 && vx1) ? im[cy0 + cx1] : 0.0f;
                float v10 = (vy1 && vx0) ? im[cy1 + cx0] : 0.0f;
                float v11 = (vy1 && vx1) ? im[cy1 + cx1] : 0.0f;
                float val = (1.0f - wy[q]) * ((1.0f - wx[q]) * v00 + wx[q] * v01) +
                            wy[q] * ((1.0f - wx[q]) * v10 + wx[q] * v11);
                float o = val * ct + hs + br;
                v[c][q] = fminf(fmaxf(o, -1.0f), 1.0f);
            }
        }
    }

    // light spot (row-constant di)
    float xf = g_light[0], yf = g_light[1], rml = g_light[2];
    float di = (float)i - xf;
    float di2 = di * di;

    float lum[4], light[4];
#pragma unroll
    for (int q = 0; q < 4; q++) {
        lum[q] = (0.3f * v[0][q] + 0.6f * v[1][q] + 0.1f * v[2][q]) *
                 (1.0f / 3.0f);
        float dj = (float)(j0 + q) - yf;
        float dl = sqrtf(di2 + dj * dj);
        float lw = 1.0f - dl * rml;
        light[q] = (lw > 0.0f) ? lw : 0.0f;
    }

    const float kn = 0.031622776601683794f;  // sqrt(0.001)
#pragma unroll
    for (int c = 0; c < 3; c++) {
        float4 o4;
        float* op = &o4.x;
        const float* nzp = &nz[c].x;
        const float* mop = &mo[c].x;
#pragma unroll
        for (int q = 0; q < 4; q++) {
            op[q] = 0.7f * v[c][q] + 0.3f * lum[q] + light[q] +
                    mop[q] * 0.2f + kn * nzp[q];
        }
        size_t off = base + (size_t)c * HW;
        __stcs(reinterpret_cast<float4*>(out + off), o4);
        __stcs(reinterpret_cast<float4*>(out + n_img + off), cv[c]);
    }
}

// ---------------------------------------------------------------------------
// Inputs (metadata order): 0 imgs, 1 cover, 2 dst_offsets, 3 hue_shift,
// 4 bright, 5 contrast, 6 light_xy(int32), 7 moire_theta, 8 moire_center,
// 9 noise. Output: [noised | cover], 2 * 32*3*512*512 floats.
// ---------------------------------------------------------------------------
extern "C" void kernel_launch(void* const* d_in, const int* in_sizes, int n_in,
                              void* d_out, int out_size) {
    const float* imgs        = (const float*)d_in[0];
    const float* cover       = (const float*)d_in[1];
    const float* dst_offsets = (const float*)d_in[2];
    const float* hue_shift   = (const float*)d_in[3];
    const float* bright      = (const float*)d_in[4];
    const float* contrast    = (const float*)d_in[5];
    const int*   light_xy    = (const int*)d_in[6];
    const float* moire_theta = (const float*)d_in[7];
    const float* moire_cent  = (const float*)d_in[8];
    const float* noise       = (const float*)d_in[9];
    float* out = (float*)d_out;

    prep_kernel<<<(CC * HW + 1023) / 1024, 256>>>(moire_theta, moire_cent,
                                                  dst_offsets, light_xy);

    dim3 grid(HW / (256 * 4), BB);
    main_kernel<<<grid, 256>>>(imgs, noise, cover, hue_shift, bright, contrast,
                               out);
}

// round 9
// speedup vs baseline: 1.3154x; 1.3154x over previous
#include <cuda_runtime.h>
#include <math.h>

#define BB 32
#define CC 3
#define HH 512
#define WW 512
#define HW (HH * WW)
#define PI_F 3.14159f

// Scratch: per-batch inverse homographies, light params, batch-invariant
// moire field (3 MB, L2-resident, reused 32x).
__device__ float g_minv[BB][9];
__device__ float g_light[3];   // xf, yf, 1/max_len
__device__ float g_moire[CC * HW];

// ---------------------------------------------------------------------------
// Prep: moire field (8 px/thread, 2x float4 stores, fast-math cos) + block-0
// side jobs: closed-form (Heckbert) homography per batch in fp32 and light
// params. Homography is unique up to scale and only used through a
// perspective divide, so the adjugate (un-normalized inverse) suffices.
// ---------------------------------------------------------------------------
__global__ void prep_kernel(const float* __restrict__ theta,
                            const float* __restrict__ center,
                            const float* __restrict__ dst_offsets,
                            const int* __restrict__ light_xy) {
    if (blockIdx.x == 0) {
        int b = threadIdx.x;
        if (b == 32) {
            float xf = (float)light_xy[0];
            float yf = (float)light_xy[1];
            const float S = 512.0f;
            float d0 = sqrtf(xf * xf + yf * yf);
            float d1 = sqrtf((xf - S) * (xf - S) + yf * yf);
            float d2 = sqrtf(xf * xf + (yf - S) * (yf - S));
            float d3 = sqrtf((xf - S) * (xf - S) + (yf - S) * (yf - S));
            float ml = fmaxf(fmaxf(d0, d1), fmaxf(d2, d3)) * 0.5f;
            g_light[0] = xf;
            g_light[1] = yf;
            g_light[2] = 1.0f / ml;
        }
        if (b < BB) {
            const float S = 512.0f;
            // src corners: k=0:(0,0) k=1:(0,S) k=2:(S,0) k=3:(S,S)
            const float sxc[4] = {0.0f, 0.0f, 512.0f, 512.0f};
            const float syc[4] = {0.0f, 512.0f, 0.0f, 512.0f};
            float du[4], dv[4];
            for (int k = 0; k < 4; k++) {
                du[k] = sxc[k] + dst_offsets[(b * 4 + k) * 2 + 0];
                dv[k] = syc[k] + dst_offsets[(b * 4 + k) * 2 + 1];
            }
            // Unit-square param: (0,0)->dst0 (1,0)->dst2 (1,1)->dst3 (0,1)->dst1
            float u0 = du[0], u1 = du[2], u2 = du[3], u3 = du[1];
            float v0 = dv[0], v1 = dv[2], v2 = dv[3], v3 = dv[1];
            float sx = u0 - u1 + u2 - u3;
            float sy = v0 - v1 + v2 - v3;
            float dx1 = u1 - u2, dx2 = u3 - u2;
            float dy1 = v1 - v2, dy2 = v3 - v2;
            float den = dx1 * dy2 - dy1 * dx2;
            float g = (sx * dy2 - sy * dx2) / den;
            float h = (dx1 * sy - dy1 * sx) / den;
            float a = u1 - u0 + g * u1;
            float bq = u3 - u0 + h * u3;
            float c = u0;
            float d = v1 - v0 + g * v1;
            float e = v3 - v0 + h * v3;
            float f = v0;
            float m0 = a,  m1 = bq, m2 = c * S;
            float m3 = d,  m4 = e,  m5 = f * S;
            float m6 = g,  m7 = h,  m8 = S;
            float inv9[9] = {
                m4 * m8 - m5 * m7, m2 * m7 - m1 * m8, m1 * m5 - m2 * m4,
                m5 * m6 - m3 * m8, m0 * m8 - m2 * m6, m2 * m3 - m0 * m5,
                m3 * m7 - m4 * m6, m1 * m6 - m0 * m7, m0 * m4 - m1 * m3};
            float nrm = 1.0f / inv9[8];
            for (int k = 0; k < 9; k++) g_minv[b][k] = inv9[k] * nrm;
        }
    }

    int idx8 = (blockIdx.x * blockDim.x + threadIdx.x) * 8;
    if (idx8 >= CC * HW) return;
    int c = idx8 / HW;
    int rem = idx8 - c * HW;
    int i = rem >> 9;
    int j0 = rem & (WW - 1);   // 8-aligned, all 8 cols in same row

    float cx = center[c * 2 + 0];
    float cy = center[c * 2 + 1];
    float th = theta[c] / 180.0f * PI_F;
    float cth = __cosf(th), sth = __sinf(th);
    float dx = (float)i - cx;
    float dx2 = dx * dx;
    float si = sth * (float)i;

    float m8v[8];
#pragma unroll
    for (int q = 0; q < 8; q++) {
        float jj = (float)(j0 + q);
        float dy = jj - cy;
        float z1 = 0.5f + 0.5f * __cosf(2.0f * PI_F * sqrtf(dx2 + dy * dy));
        float z2 = 0.5f + 0.5f * __cosf(cth * jj + si);
        m8v[q] = fminf(z1, z2) * 2.0f - 1.0f;
    }
    *reinterpret_cast<float4*>(g_moire + idx8) =
        make_float4(m8v[0], m8v[1], m8v[2], m8v[3]);
    *reinterpret_cast<float4*>(g_moire + idx8 + 4) =
        make_float4(m8v[4], m8v[5], m8v[6], m8v[7]);
}

// ---------------------------------------------------------------------------
// Fused main kernel (R7 configuration — measured best): 2 px/thread, float2
// streaming I/O with evict-streaming hints, interior fast path for bilinear
// taps, cover pass-through folded in.
// ---------------------------------------------------------------------------
__global__ void __launch_bounds__(256, 6)
main_kernel(const float* __restrict__ imgs,
            const float* __restrict__ noise,
            const float* __restrict__ cover,
            const float* __restrict__ hue_shift,
            const float* __restrict__ bright,
            const float* __restrict__ contrast,
            float* __restrict__ out) {
    int t = blockIdx.x * blockDim.x + threadIdx.x;
    int p2 = t * 2;                 // first pixel of the pair
    if (p2 >= HW) return;
    int b = blockIdx.y;
    int i = p2 >> 9;                // row (same for both pixels)
    int j0 = p2 & (WW - 1);

    const size_t n_img = (size_t)BB * CC * HW;
    size_t base = (size_t)b * CC * HW + p2;

    // Streaming loads first (independent of the gather chain; no L2 reuse ->
    // evict-streaming policy).
    float2 nz[3], cv[3], mo[3];
#pragma unroll
    for (int c = 0; c < 3; c++) {
        nz[c] = __ldcs(reinterpret_cast<const float2*>(noise + base + (size_t)c * HW));
        cv[c] = __ldcs(reinterpret_cast<const float2*>(cover + base + (size_t)c * HW));
        mo[c] = __ldg(reinterpret_cast<const float2*>(g_moire + c * HW + p2));
    }

    // Projective map (row-constant parts hoisted).
    const float* mv = g_minv[b];
    float y = (float)i;
    float cA = mv[1] * y + mv[2];
    float cB = mv[4] * y + mv[5];
    float cW = mv[7] * y + mv[8];

    int ix0[2], iy0[2];
    float wx[2], wy[2];
    bool interior = true;
#pragma unroll
    for (int q = 0; q < 2; q++) {
        float x = (float)(j0 + q);
        float invw = __fdividef(1.0f, mv[6] * x + cW);
        float sxv = (mv[0] * x + cA) * invw;
        float syv = (mv[3] * x + cB) * invw;
        float x0f = floorf(sxv), y0f = floorf(syv);
        wx[q] = sxv - x0f;
        wy[q] = syv - y0f;
        ix0[q] = (int)x0f;
        iy0[q] = (int)y0f;
        interior &= ((unsigned)ix0[q] <= (unsigned)(WW - 2)) &&
                    ((unsigned)iy0[q] <= (unsigned)(HH - 2));
    }

    float ct = contrast[b];
    float br = bright[b];
    float hs0 = hue_shift[b * 3 + 0];
    float hs1 = hue_shift[b * 3 + 1];
    float hs2 = hue_shift[b * 3 + 2];

    const float* imb = imgs + (size_t)b * CC * HW;
    float v[3][2];
    if (interior) {
        // Fast path: all taps in-bounds, raw indices, no masks.
        int o00[2], o10[2];
#pragma unroll
        for (int q = 0; q < 2; q++) {
            o00[q] = iy0[q] * WW + ix0[q];
            o10[q] = o00[q] + WW;
        }
#pragma unroll
        for (int c = 0; c < 3; c++) {
            const float* im = imb + c * HW;
            float hs = (c == 0) ? hs0 : ((c == 1) ? hs1 : hs2);
#pragma unroll
            for (int q = 0; q < 2; q++) {
                float v00 = im[o00[q]];
                float v01 = im[o00[q] + 1];
                float v10 = im[o10[q]];
                float v11 = im[o10[q] + 1];
                float top = v00 + wx[q] * (v01 - v00);
                float bot = v10 + wx[q] * (v11 - v10);
                float val = top + wy[q] * (bot - top);
                float o = val * ct + hs + br;
                v[c][q] = fminf(fmaxf(o, -1.0f), 1.0f);
            }
        }
    } else {
        // Boundary path: kornia zero-padding semantics (mask, clamp).
#pragma unroll
        for (int c = 0; c < 3; c++) {
            const float* im = imb + c * HW;
            float hs = (c == 0) ? hs0 : ((c == 1) ? hs1 : hs2);
#pragma unroll
            for (int q = 0; q < 2; q++) {
                int x0 = ix0[q], y0 = iy0[q];
                int x1 = x0 + 1, y1 = y0 + 1;
                bool vx0 = (x0 >= 0) && (x0 < WW);
                bool vx1 = (x1 >= 0) && (x1 < WW);
                bool vy0 = (y0 >= 0) && (y0 < HH);
                bool vy1 = (y1 >= 0) && (y1 < HH);
                int cx0 = min(max(x0, 0), WW - 1);
                int cx1 = min(max(x1, 0), WW - 1);
                int cy0 = min(max(y0, 0), HH - 1) * WW;
                int cy1 = min(max(y1, 0), HH - 1) * WW;
                float v00 = (vy0 && vx0) ? im[cy0 + cx0] : 0.0f;
                float v01 = (vy0 && vx1) ? im[cy0 + cx1] : 0.0f;
                float v10 = (vy1 && vx0) ? im[cy1 + cx0] : 0.0f;
                float v11 = (vy1 && vx1) ? im[cy1 + cx1] : 0.0f;
                float val = (1.0f - wy[q]) * ((1.0f - wx[q]) * v00 + wx[q] * v01) +
                            wy[q] * ((1.0f - wx[q]) * v10 + wx[q] * v11);
                float o = val * ct + hs + br;
                v[c][q] = fminf(fmaxf(o, -1.0f), 1.0f);
            }
        }
    }

    // light spot (row-constant di)
    float xf = g_light[0], yf = g_light[1], rml = g_light[2];
    float di = (float)i - xf;
    float di2 = di * di;

    float lum[2], light[2];
#pragma unroll
    for (int q = 0; q < 2; q++) {
        lum[q] = (0.3f * v[0][q] + 0.6f * v[1][q] + 0.1f * v[2][q]) *
                 (1.0f / 3.0f);
        float dj = (float)(j0 + q) - yf;
        float dl = sqrtf(di2 + dj * dj);
        float lw = 1.0f - dl * rml;
        light[q] = (lw > 0.0f) ? lw : 0.0f;
    }

    const float kn = 0.031622776601683794f;  // sqrt(0.001)
#pragma unroll
    for (int c = 0; c < 3; c++) {
        float2 o2;
        o2.x = 0.7f * v[c][0] + 0.3f * lum[0] + light[0] + mo[c].x * 0.2f +
               kn * nz[c].x;
        o2.y = 0.7f * v[c][1] + 0.3f * lum[1] + light[1] + mo[c].y * 0.2f +
               kn * nz[c].y;
        size_t off = base + (size_t)c * HW;
        __stcs(reinterpret_cast<float2*>(out + off), o2);
        __stcs(reinterpret_cast<float2*>(out + n_img + off), cv[c]);
    }
}

// ---------------------------------------------------------------------------
// Inputs (metadata order): 0 imgs, 1 cover, 2 dst_offsets, 3 hue_shift,
// 4 bright, 5 contrast, 6 light_xy(int32), 7 moire_theta, 8 moire_center,
// 9 noise. Output: [noised | cover], 2 * 32*3*512*512 floats.
// ---------------------------------------------------------------------------
extern "C" void kernel_launch(void* const* d_in, const int* in_sizes, int n_in,
                              void* d_out, int out_size) {
    const float* imgs        = (const float*)d_in[0];
    const float* cover       = (const float*)d_in[1];
    const float* dst_offsets = (const float*)d_in[2];
    const float* hue_shift   = (const float*)d_in[3];
    const float* bright      = (const float*)d_in[4];
    const float* contrast    = (const float*)d_in[5];
    const int*   light_xy    = (const int*)d_in[6];
    const float* moire_theta = (const float*)d_in[7];
    const float* moire_cent  = (const float*)d_in[8];
    const float* noise       = (const float*)d_in[9];
    float* out = (float*)d_out;

    prep_kernel<<<(CC * HW + 2047) / 2048, 256>>>(moire_theta, moire_cent,
                                                  dst_offsets, light_xy);

    dim3 grid(HW / (256 * 2), BB);
    main_kernel<<<grid, 256>>>(imgs, noise, cover, hue_shift, bright, contrast,
                               out);
}